// round 14
// baseline (speedup 1.0000x reference)
#include <cuda_runtime.h>
#include <cuda_bf16.h>

#define MAXB 8192
// SoA per-block partials: g_part[c*MAXB + b]
__device__ float g_part[5 * MAXB];
__device__ unsigned int g_ticket = 0;

// 2-exp focal: ce = log(1 + e^(xa-xl) + e^(xb-xl)), pt = 1/s
__device__ __forceinline__ float focal3(float x0, float x1, float x2, int lab, float& cnt) {
    if (lab == -100) return 0.0f;
    float xl = (lab == 0) ? x0 : ((lab == 1) ? x1 : x2);
    float xa = (lab == 0) ? x1 : x0;
    float xb = (lab == 2) ? x1 : x2;
    float s  = 1.0f + __expf(xa - xl) + __expf(xb - xl);
    float ce = __logf(s);
    float pt = __fdividef(1.0f, s);
    float u  = 1.0f - pt;
    cnt += 1.0f;
    return u * u * ce;
}

__device__ __forceinline__ float bce_lin(float z, float y, float& lp) {
    lp *= (1.0f + __expf(-fabsf(z)));
    return fmaxf(z, 0.0f) - z * y;
}
__device__ __forceinline__ float blabel_s(int a, int o) {
    return ((a == 1) | (o == 1)) ? 1.0f : 0.0f;
}
__device__ __forceinline__ float blabel_e(int a, int an, int o, int on) {
    return (((a == 2) & (an != 2)) | ((o == 2) & (on != 2))) ? 1.0f : 0.0f;
}

__global__ void
fused_loss_kernel(const float* __restrict__ al, const float* __restrict__ ol,
                  const float* __restrict__ bl,
                  const int* __restrict__ la, const int* __restrict__ lo,
                  const float* __restrict__ sl, const int* __restrict__ ls,
                  float* __restrict__ out,
                  int total4, int S, int Bn, int total) {
    int t = blockIdx.x * blockDim.x + threadIdx.x;
    const int stride = gridDim.x * blockDim.x;
    float v0 = 0.f, v1 = 0.f, v2 = 0.f, v3 = 0.f, v4 = 0.f;

    // ---- prefetch buffers (next iteration's data) ----
    int4  pA = make_int4(0,0,0,0), pO = make_int4(0,0,0,0);
    float4 pa0, pa1, pa2, pb0, pb1, pb2, pz0, pz1;

    bool valid = (t < total4);
    if (valid) {
        pA  = reinterpret_cast<const int4*>(la)[t];
        pO  = reinterpret_cast<const int4*>(lo)[t];
        const float4* ap = reinterpret_cast<const float4*>(al) + (size_t)t * 3;
        pa0 = ap[0]; pa1 = ap[1]; pa2 = ap[2];
        const float4* op = reinterpret_cast<const float4*>(ol) + (size_t)t * 3;
        pb0 = op[0]; pb1 = op[1]; pb2 = op[2];
        const float4* bp = reinterpret_cast<const float4*>(bl) + (size_t)t * 2;
        pz0 = bp[0]; pz1 = bp[1];
    }

    while (valid) {
        // move prefetched -> current
        int tc = t;
        int4 A4 = pA, O4 = pO;
        float4 a0 = pa0, a1 = pa1, a2 = pa2;
        float4 b0 = pb0, b1 = pb1, b2 = pb2;
        float4 z0 = pz0, z1 = pz1;

        // ---- issue next iteration's loads NOW (overlap with compute below) ----
        t += stride;
        valid = (t < total4);
        if (valid) {
            pA  = reinterpret_cast<const int4*>(la)[t];
            pO  = reinterpret_cast<const int4*>(lo)[t];
            const float4* ap = reinterpret_cast<const float4*>(al) + (size_t)t * 3;
            pa0 = ap[0]; pa1 = ap[1]; pa2 = ap[2];
            const float4* op = reinterpret_cast<const float4*>(ol) + (size_t)t * 3;
            pb0 = op[0]; pb1 = op[1]; pb2 = op[2];
            const float4* bp = reinterpret_cast<const float4*>(bl) + (size_t)t * 2;
            pz0 = bp[0]; pz1 = bp[1];
        }

        // ---- compute current iteration (4 positions) ----
        int base = tc * 4;

        v0 += focal3(a0.x, a0.y, a0.z, A4.x, v3);
        v0 += focal3(a0.w, a1.x, a1.y, A4.y, v3);
        v0 += focal3(a1.z, a1.w, a2.x, A4.z, v3);
        v0 += focal3(a2.y, a2.z, a2.w, A4.w, v3);

        v1 += focal3(b0.x, b0.y, b0.z, O4.x, v4);
        v1 += focal3(b0.w, b1.x, b1.y, O4.y, v4);
        v1 += focal3(b1.z, b1.w, b2.x, O4.z, v4);
        v1 += focal3(b2.y, b2.z, b2.w, O4.w, v4);

        // next-label for position 3 of this chunk
        int s3 = base - (base / S) * S + 3;
        int nA = -1, nO = -1;
        if (s3 != S - 1) { nA = la[base + 4]; nO = lo[base + 4]; }

        float lp = 1.0f;
        v2 += bce_lin(z0.x, blabel_s(A4.x, O4.x), lp);
        v2 += bce_lin(z0.y, blabel_e(A4.x, A4.y, O4.x, O4.y), lp);
        v2 += bce_lin(z0.z, blabel_s(A4.y, O4.y), lp);
        v2 += bce_lin(z0.w, blabel_e(A4.y, A4.z, O4.y, O4.z), lp);
        v2 += bce_lin(z1.x, blabel_s(A4.z, O4.z), lp);
        v2 += bce_lin(z1.y, blabel_e(A4.z, A4.w, O4.z, O4.w), lp);
        v2 += bce_lin(z1.z, blabel_s(A4.w, O4.w), lp);
        v2 += bce_lin(z1.w, blabel_e(A4.w, nA, O4.w, nO), lp);
        v2 += __logf(lp);   // 8 log1p terms in one LG2
    }

    // warp reduce
    #pragma unroll
    for (int off = 16; off; off >>= 1) {
        v0 += __shfl_down_sync(0xffffffffu, v0, off);
        v1 += __shfl_down_sync(0xffffffffu, v1, off);
        v2 += __shfl_down_sync(0xffffffffu, v2, off);
        v3 += __shfl_down_sync(0xffffffffu, v3, off);
        v4 += __shfl_down_sync(0xffffffffu, v4, off);
    }

    // deterministic block reduce
    __shared__ float sw[8][5];
    int wid = threadIdx.x >> 5;
    if ((threadIdx.x & 31) == 0) {
        sw[wid][0] = v0; sw[wid][1] = v1; sw[wid][2] = v2;
        sw[wid][3] = v3; sw[wid][4] = v4;
    }
    __syncthreads();

    __shared__ bool s_last;
    if (threadIdx.x == 0) {
        float s0 = 0.f, s1 = 0.f, s2 = 0.f, s3 = 0.f, s4 = 0.f;
        #pragma unroll
        for (int w = 0; w < 8; w++) {
            s0 += sw[w][0]; s1 += sw[w][1]; s2 += sw[w][2];
            s3 += sw[w][3]; s4 += sw[w][4];
        }
        g_part[0 * MAXB + blockIdx.x] = s0;
        g_part[1 * MAXB + blockIdx.x] = s1;
        g_part[2 * MAXB + blockIdx.x] = s2;
        g_part[3 * MAXB + blockIdx.x] = s3;
        g_part[4 * MAXB + blockIdx.x] = s4;
        __threadfence();
        unsigned int ticket = atomicInc(&g_ticket, 0xffffffffu);
        s_last = (ticket == gridDim.x - 1);
    }
    __syncthreads();
    if (!s_last) return;

    // ---- last block: final reduction, all-float ----
    int nblocks = gridDim.x;
    float d0 = 0.f, d1 = 0.f, d2 = 0.f, d3 = 0.f, d4 = 0.f;
    for (int b = threadIdx.x; b < nblocks; b += blockDim.x) {
        d0 += g_part[0 * MAXB + b];
        d1 += g_part[1 * MAXB + b];
        d2 += g_part[2 * MAXB + b];
        d3 += g_part[3 * MAXB + b];
        d4 += g_part[4 * MAXB + b];
    }

    // sentiment CE (tiny)
    float ce = 0.f, val = 0.f;
    for (int b = threadIdx.x; b < Bn; b += blockDim.x) {
        int lab = ls[b];
        if (lab != -100) {
            float x0 = sl[3*b], x1 = sl[3*b+1], x2 = sl[3*b+2];
            float lse = __logf(__expf(x0) + __expf(x1) + __expf(x2));
            float xl = (lab == 0) ? x0 : ((lab == 1) ? x1 : x2);
            ce += lse - xl;
            val += 1.0f;
        }
    }

    #pragma unroll
    for (int off = 16; off; off >>= 1) {
        d0 += __shfl_down_sync(0xffffffffu, d0, off);
        d1 += __shfl_down_sync(0xffffffffu, d1, off);
        d2 += __shfl_down_sync(0xffffffffu, d2, off);
        d3 += __shfl_down_sync(0xffffffffu, d3, off);
        d4 += __shfl_down_sync(0xffffffffu, d4, off);
        ce  += __shfl_down_sync(0xffffffffu, ce, off);
        val += __shfl_down_sync(0xffffffffu, val, off);
    }
    __shared__ float sd[8][7];
    if ((threadIdx.x & 31) == 0) {
        sd[wid][0] = d0; sd[wid][1] = d1; sd[wid][2] = d2;
        sd[wid][3] = d3; sd[wid][4] = d4;
        sd[wid][5] = ce; sd[wid][6] = val;
    }
    __syncthreads();
    if (threadIdx.x == 0) {
        float t0 = 0, t1 = 0, t2 = 0, t3 = 0, t4 = 0, tce = 0, tva = 0;
        #pragma unroll
        for (int w = 0; w < 8; w++) {
            t0 += sd[w][0]; t1 += sd[w][1]; t2 += sd[w][2];
            t3 += sd[w][3]; t4 += sd[w][4];
            tce += sd[w][5]; tva += sd[w][6];
        }
        float fa   = (t3 > 0.0f) ? t0 / fmaxf(t3, 1.0f) : 0.0f;
        float fo   = (t4 > 0.0f) ? t1 / fmaxf(t4, 1.0f) : 0.0f;
        float sent = tce / fmaxf(tva, 1.0f);
        float bnd  = t2 / ((float)total * 2.0f);
        out[0] = fa + fo + sent + 0.5f * bnd;
        g_ticket = 0;   // reset for next graph replay
    }
}

extern "C" void kernel_launch(void* const* d_in, const int* in_sizes, int n_in,
                              void* d_out, int out_size) {
    const float* aspect_logits    = (const float*)d_in[0];
    const float* opinion_logits   = (const float*)d_in[1];
    const float* sentiment_logits = (const float*)d_in[2];
    const float* boundary_logits  = (const float*)d_in[3];
    const int*   aspect_labels    = (const int*)d_in[4];
    const int*   opinion_labels   = (const int*)d_in[5];
    const int*   sentiment_labels = (const int*)d_in[6];
    float* out = (float*)d_out;

    int B = in_sizes[2] / 3;       // sentiment_logits = B*3
    int total = in_sizes[4];       // aspect_labels = B*S
    int S = total / B;

    int total4  = total / 4;       // divisible: B*S = 2^21
    int threads = 256;
    // grid-stride: 4 iterations per thread -> continuous pipelined loads
    int blocks  = (total4 + threads * 4 - 1) / (threads * 4);   // 512
    if (blocks > MAXB) blocks = MAXB;

    fused_loss_kernel<<<blocks, threads>>>(aspect_logits, opinion_logits,
                                           boundary_logits, aspect_labels,
                                           opinion_labels, sentiment_logits,
                                           sentiment_labels, out,
                                           total4, S, B, total);
}